// round 16
// baseline (speedup 1.0000x reference)
#include <cuda_runtime.h>
#include <cstdint>

#define N_POINTS_C 1048576
#define N_LEVELS_C 16
#define LOG2_T_C 19
#define T_C (1u << LOG2_T_C)
#define TMASK_C (T_C - 1u)

#define NBUCKETS 32768     // 32^3 spatial buckets, mean 32 points each
#define CAP 64             // slots per bucket
#define MAIN_SLOTS (NBUCKETS * CAP)   // 2097152
#define OVF_CAP 65536
#define IDX_OVF NBUCKETS

__constant__ int c_res[N_LEVELS_C] = {
    16, 20, 25, 32, 40, 50, 64, 80, 101, 128, 161, 203, 256, 322, 406, 512
};

// Scratch (device globals: allocation-free).
__device__ unsigned int g_cnt[NBUCKETS + 1];
__device__ float4       g_slots[MAIN_SLOTS];  // 32MB bucketed points
__device__ float4       g_ovf[OVF_CAP];       // overflow points

__device__ __forceinline__ int bucket_of(float px, float py, float pz) {
    int bx = (int)(px * 32.0f); bx = bx > 31 ? 31 : (bx < 0 ? 0 : bx);
    int by = (int)(py * 32.0f); by = by > 31 ? 31 : (by < 0 ? 0 : by);
    int bz = (int)(pz * 32.0f); bz = bz > 31 ? 31 : (bz < 0 ? 0 : bz);
    return (bz << 10) | (by << 5) | bx;
}

// 4 points per thread: 3 coalesced float4 reads, 4 independent atomic->store chains.
__global__ void scatter_kernel(const float* __restrict__ x) {
    const int i = blockIdx.x * blockDim.x + threadIdx.x;   // 0 .. N/4-1
    const float4* __restrict__ x4 = reinterpret_cast<const float4*>(x);
    const float4 A = __ldg(&x4[3 * i + 0]);
    const float4 B = __ldg(&x4[3 * i + 1]);
    const float4 C = __ldg(&x4[3 * i + 2]);

    float4 rec[4];
    rec[0] = make_float4(A.x, A.y, A.z, __int_as_float(4 * i + 0));
    rec[1] = make_float4(A.w, B.x, B.y, __int_as_float(4 * i + 1));
    rec[2] = make_float4(B.z, B.w, C.x, __int_as_float(4 * i + 2));
    rec[3] = make_float4(C.y, C.z, C.w, __int_as_float(4 * i + 3));

    unsigned pos[4];
    int bkt[4];
#pragma unroll
    for (int k = 0; k < 4; k++) {
        bkt[k] = bucket_of(rec[k].x, rec[k].y, rec[k].z);
        pos[k] = atomicAdd(&g_cnt[bkt[k]], 1u);
    }
#pragma unroll
    for (int k = 0; k < 4; k++) {
        if (pos[k] < CAP) {
            g_slots[bkt[k] * CAP + pos[k]] = rec[k];
        } else {
            unsigned o = atomicAdd(&g_cnt[IDX_OVF], 1u);
            if (o < OVF_CAP) g_ovf[o] = rec[k];
        }
    }
}

// 2 threads per point: lane 2i -> levels 0..7, lane 2i+1 -> levels 8..15.
// Adjacent lanes write the two 64B halves of the same output row, so each
// STG.128 touches 16 distinct 128B lines instead of 32 (no shuffles needed).
__global__ void __launch_bounds__(256, 8) hashgrid_kernel(
    const float* __restrict__ emb,
    float* __restrict__ out)
{
    const int t = blockIdx.x * blockDim.x + threadIdx.x;
    const int half = t & 1;            // which 8-level half this thread owns
    const int sl = t >> 1;             // slot index (shared by lane pair)

    float4 p;
    if (sl < MAIN_SLOTS) {
        const int b = sl >> 6;
        const int s = sl & 63;
        unsigned int c = g_cnt[b];     // broadcast within warp
        if (c > CAP) c = CAP;
        if ((unsigned)s >= c) return;
        p = g_slots[sl];               // pair lanes read same slot (broadcast)
    } else {
        unsigned int o = (unsigned)(sl - MAIN_SLOTS);
        unsigned int oc = g_cnt[IDX_OVF];
        if (oc > OVF_CAP) oc = OVF_CAP;
        if (o >= oc) return;
        p = g_ovf[o];
    }

    const float px = p.x, py = p.y, pz = p.z;
    const int  oidx = __float_as_int(p.w);

    // this thread's 4 float4 quarters: offsets half*64B .. half*64+48B
    float4* __restrict__ ohalf =
        reinterpret_cast<float4*>(out + (size_t)oidx * 32 + half * 16);

    const int lbase = half * 8;

    float accpair[4];   // 2 levels' worth, flushed every 2 levels

#pragma unroll
    for (int j = 0; j < 8; j++) {
        const int l = lbase + j;
        const int res = c_res[l];
        const float rf = (float)(res - 1);

        const float sx = px * rf;
        const float sy = py * rf;
        const float sz = pz * rf;

        int fx = (int)sx; fx = fx > res - 2 ? res - 2 : fx; fx = fx < 0 ? 0 : fx;
        int fy = (int)sy; fy = fy > res - 2 ? res - 2 : fy; fy = fy < 0 ? 0 : fy;
        int fz = (int)sz; fz = fz > res - 2 ? res - 2 : fz; fz = fz < 0 ? 0 : fz;

        const float tx = sx - (float)fx;
        const float ty = sy - (float)fy;
        const float tz = sz - (float)fz;
        const float ux = 1.0f - tx;
        const float uy = 1.0f - ty;
        const float uz = 1.0f - tz;

        const unsigned hy0 = (unsigned)fy * 2654435761u;
        const unsigned hy1 = hy0 + 2654435761u;
        const unsigned hz0 = (unsigned)fz * 805459861u;
        const unsigned hz1 = hz0 + 805459861u;

        // x-pair trick: even base e = fx & ~1; entries h(e) and h(e)^1 form
        // one aligned float4. Odd lanes also need corner e+2 (predicated).
        const unsigned e   = (unsigned)(fx & ~1);
        const bool     odd = (fx & 1) != 0;

        // x-corner weights by entry index: corner e, e+1, e+2
        const float w_e  = odd ? 0.0f : ux;
        const float w_e1 = odd ? ux   : tx;
        const float w_e2 = odd ? tx   : 0.0f;

        // entry parity of he for pair (yb,zb) is (fy^fz^yb^zb)&1:
        // parity 0 -> q.lo holds corner e ; parity 1 -> q.lo holds corner e+1
        const bool par = ((fy ^ fz) & 1) != 0;
        const float wloA = par ? w_e1 : w_e;   // pairs with yb^zb==0
        const float whiA = par ? w_e  : w_e1;
        const float wloB = whiA;               // pairs with yb^zb==1
        const float whiB = wloA;

        const float2* __restrict__ tab =
            reinterpret_cast<const float2*>(emb) + (size_t)l * T_C;
        const float4* __restrict__ tab4 =
            reinterpret_cast<const float4*>(tab);

        float a0 = 0.0f, a1 = 0.0f;

#pragma unroll
        for (int g = 0; g < 2; g++) {          // g = zb
            const unsigned hz = g ? hz1 : hz0;
            const float    wz = g ? tz  : uz;

            const unsigned m0 = hy0 ^ hz;      // yb=0
            const unsigned m1 = hy1 ^ hz;      // yb=1

            const unsigned he0 = (e ^ m0) & TMASK_C;
            const unsigned he1 = (e ^ m1) & TMASK_C;

            float4 q0 = __ldg(&tab4[he0 >> 1]);
            float4 q1 = __ldg(&tab4[he1 >> 1]);

            float2 v20 = make_float2(0.0f, 0.0f);
            float2 v21 = make_float2(0.0f, 0.0f);
            if (odd) {
                v20 = __ldg(&tab[((e + 2u) ^ m0) & TMASK_C]);
                v21 = __ldg(&tab[((e + 2u) ^ m1) & TMASK_C]);
            }

            // pair (yb=0, zb=g): yb^zb = g ; pair (yb=1, zb=g): yb^zb = !g
            const float wlo0 = g ? wloB : wloA;
            const float whi0 = g ? whiB : whiA;
            const float wlo1 = g ? wloA : wloB;
            const float whi1 = g ? whiA : whiB;

            const float wyz0 = uy * wz;
            const float wyz1 = ty * wz;

            a0 += wyz0 * (wlo0 * q0.x + whi0 * q0.z + w_e2 * v20.x);
            a1 += wyz0 * (wlo0 * q0.y + whi0 * q0.w + w_e2 * v20.y);
            a0 += wyz1 * (wlo1 * q1.x + whi1 * q1.z + w_e2 * v21.x);
            a1 += wyz1 * (wlo1 * q1.y + whi1 * q1.w + w_e2 * v21.y);
        }

        accpair[2 * (j & 1) + 0] = a0;
        accpair[2 * (j & 1) + 1] = a1;
        if (j & 1) {
            // pair lanes hit the same 128B output line (offsets half*64 + 16q)
            ohalf[j >> 1] = make_float4(accpair[0], accpair[1],
                                        accpair[2], accpair[3]);
        }
    }
}

extern "C" void kernel_launch(void* const* d_in, const int* in_sizes, int n_in,
                              void* d_out, int out_size)
{
    const float* x = (const float*)d_in[0];
    const float* emb = (const float*)d_in[1];
    float* out = (float*)d_out;

    const int threads = 256;

    void* cnt_ptr = nullptr;
    cudaGetSymbolAddress(&cnt_ptr, g_cnt);
    cudaMemsetAsync(cnt_ptr, 0, (NBUCKETS + 1) * sizeof(unsigned int));

    scatter_kernel<<<(N_POINTS_C / 4) / threads, threads>>>(x);

    const int main_blocks = 2 * (MAIN_SLOTS + OVF_CAP) / threads;  // 16896
    hashgrid_kernel<<<main_blocks, threads>>>(emb, out);
}

// round 17
// speedup vs baseline: 1.0559x; 1.0559x over previous
#include <cuda_runtime.h>
#include <cstdint>

#define N_POINTS_C 1048576
#define N_LEVELS_C 16
#define LOG2_T_C 19
#define T_C (1u << LOG2_T_C)
#define TMASK_C (T_C - 1u)

#define NBUCKETS 32768     // 32^3 spatial buckets, mean 32 points each
#define CAP 64             // slots per bucket
#define MAIN_SLOTS (NBUCKETS * CAP)   // 2097152
#define OVF_CAP 65536
#define IDX_OVF NBUCKETS

__constant__ int c_res[N_LEVELS_C] = {
    16, 20, 25, 32, 40, 50, 64, 80, 101, 128, 161, 203, 256, 322, 406, 512
};

// Scratch (device globals: allocation-free).
__device__ unsigned int g_cnt[NBUCKETS + 1];
__device__ float4       g_slots[MAIN_SLOTS];  // 32MB bucketed points
__device__ float4       g_ovf[OVF_CAP];       // overflow points

__device__ __forceinline__ int bucket_of(float px, float py, float pz) {
    int bx = (int)(px * 32.0f); bx = bx > 31 ? 31 : (bx < 0 ? 0 : bx);
    int by = (int)(py * 32.0f); by = by > 31 ? 31 : (by < 0 ? 0 : by);
    int bz = (int)(pz * 32.0f); bz = bz > 31 ? 31 : (bz < 0 ? 0 : bz);
    return (bz << 10) | (by << 5) | bx;
}

// 4 points per thread: 3 coalesced float4 reads, 4 independent atomic->store chains.
__global__ void scatter_kernel(const float* __restrict__ x) {
    const int i = blockIdx.x * blockDim.x + threadIdx.x;   // 0 .. N/4-1
    const float4* __restrict__ x4 = reinterpret_cast<const float4*>(x);
    const float4 A = __ldg(&x4[3 * i + 0]);
    const float4 B = __ldg(&x4[3 * i + 1]);
    const float4 C = __ldg(&x4[3 * i + 2]);

    float4 rec[4];
    rec[0] = make_float4(A.x, A.y, A.z, __int_as_float(4 * i + 0));
    rec[1] = make_float4(A.w, B.x, B.y, __int_as_float(4 * i + 1));
    rec[2] = make_float4(B.z, B.w, C.x, __int_as_float(4 * i + 2));
    rec[3] = make_float4(C.y, C.z, C.w, __int_as_float(4 * i + 3));

    unsigned pos[4];
    int bkt[4];
#pragma unroll
    for (int k = 0; k < 4; k++) {
        bkt[k] = bucket_of(rec[k].x, rec[k].y, rec[k].z);
        pos[k] = atomicAdd(&g_cnt[bkt[k]], 1u);
    }
#pragma unroll
    for (int k = 0; k < 4; k++) {
        if (pos[k] < CAP) {
            g_slots[bkt[k] * CAP + pos[k]] = rec[k];
        } else {
            unsigned o = atomicAdd(&g_cnt[IDX_OVF], 1u);
            if (o < OVF_CAP) g_ovf[o] = rec[k];
        }
    }
}

// 2 threads per point, interleaved-quad level split:
//   even lane: levels {0,1, 4,5, 8,9, 12,13}  -> bytes [32q,     32q+16)
//   odd  lane: levels {2,3, 6,7, 10,11,14,15} -> bytes [32q+16,  32q+32)
// The lane pair's stores land in the SAME 32B sector, so each STG.128
// instruction touches 16 distinct sectors instead of 32 (halves store wf).
__global__ void __launch_bounds__(256, 8) hashgrid_kernel(
    const float* __restrict__ emb,
    float* __restrict__ out)
{
    const int t = blockIdx.x * blockDim.x + threadIdx.x;
    const int half = t & 1;            // which interleaved level set
    const int sl = t >> 1;             // slot index (shared by lane pair)

    float4 p;
    if (sl < MAIN_SLOTS) {
        const int b = sl >> 6;
        const int s = sl & 63;
        unsigned int c = g_cnt[b];     // broadcast within warp
        if (c > CAP) c = CAP;
        if ((unsigned)s >= c) return;
        p = g_slots[sl];               // pair lanes read same slot (broadcast)
    } else {
        unsigned int o = (unsigned)(sl - MAIN_SLOTS);
        unsigned int oc = g_cnt[IDX_OVF];
        if (oc > OVF_CAP) oc = OVF_CAP;
        if (o >= oc) return;
        p = g_ovf[o];
    }

    const float px = p.x, py = p.y, pz = p.z;
    const int  oidx = __float_as_int(p.w);

    float4* __restrict__ orow4 =
        reinterpret_cast<float4*>(out + (size_t)oidx * 32);

    float accpair[4];   // 2 levels' worth, flushed every 2 levels

#pragma unroll
    for (int j = 0; j < 8; j++) {
        // level = quad*4 + half*2 + (j&1)
        const int l = ((j >> 1) << 2) + (half << 1) + (j & 1);
        const int res = c_res[l];
        const float rf = (float)(res - 1);

        const float sx = px * rf;
        const float sy = py * rf;
        const float sz = pz * rf;

        int fx = (int)sx; fx = fx > res - 2 ? res - 2 : fx; fx = fx < 0 ? 0 : fx;
        int fy = (int)sy; fy = fy > res - 2 ? res - 2 : fy; fy = fy < 0 ? 0 : fy;
        int fz = (int)sz; fz = fz > res - 2 ? res - 2 : fz; fz = fz < 0 ? 0 : fz;

        const float tx = sx - (float)fx;
        const float ty = sy - (float)fy;
        const float tz = sz - (float)fz;
        const float ux = 1.0f - tx;
        const float uy = 1.0f - ty;
        const float uz = 1.0f - tz;

        const unsigned hy0 = (unsigned)fy * 2654435761u;
        const unsigned hy1 = hy0 + 2654435761u;
        const unsigned hz0 = (unsigned)fz * 805459861u;
        const unsigned hz1 = hz0 + 805459861u;

        // x-pair trick: even base e = fx & ~1; entries h(e) and h(e)^1 form
        // one aligned float4. Odd-fx lanes also need corner e+2 (predicated).
        const unsigned e   = (unsigned)(fx & ~1);
        const bool     odd = (fx & 1) != 0;

        // x-corner weights by entry index: corner e, e+1, e+2
        const float w_e  = odd ? 0.0f : ux;
        const float w_e1 = odd ? ux   : tx;
        const float w_e2 = odd ? tx   : 0.0f;

        // entry parity of he for pair (yb,zb) is (fy^fz^yb^zb)&1:
        // parity 0 -> q.lo holds corner e ; parity 1 -> q.lo holds corner e+1
        const bool par = ((fy ^ fz) & 1) != 0;
        const float wloA = par ? w_e1 : w_e;   // pairs with yb^zb==0
        const float whiA = par ? w_e  : w_e1;
        const float wloB = whiA;               // pairs with yb^zb==1
        const float whiB = wloA;

        const float2* __restrict__ tab =
            reinterpret_cast<const float2*>(emb) + (size_t)l * T_C;
        const float4* __restrict__ tab4 =
            reinterpret_cast<const float4*>(tab);

        float a0 = 0.0f, a1 = 0.0f;

#pragma unroll
        for (int g = 0; g < 2; g++) {          // g = zb
            const unsigned hz = g ? hz1 : hz0;
            const float    wz = g ? tz  : uz;

            const unsigned m0 = hy0 ^ hz;      // yb=0
            const unsigned m1 = hy1 ^ hz;      // yb=1

            const unsigned he0 = (e ^ m0) & TMASK_C;
            const unsigned he1 = (e ^ m1) & TMASK_C;

            float4 q0 = __ldg(&tab4[he0 >> 1]);
            float4 q1 = __ldg(&tab4[he1 >> 1]);

            float2 v20 = make_float2(0.0f, 0.0f);
            float2 v21 = make_float2(0.0f, 0.0f);
            if (odd) {
                v20 = __ldg(&tab[((e + 2u) ^ m0) & TMASK_C]);
                v21 = __ldg(&tab[((e + 2u) ^ m1) & TMASK_C]);
            }

            // pair (yb=0, zb=g): yb^zb = g ; pair (yb=1, zb=g): yb^zb = !g
            const float wlo0 = g ? wloB : wloA;
            const float whi0 = g ? whiB : whiA;
            const float wlo1 = g ? wloA : wloB;
            const float whi1 = g ? whiA : whiB;

            const float wyz0 = uy * wz;
            const float wyz1 = ty * wz;

            a0 += wyz0 * (wlo0 * q0.x + whi0 * q0.z + w_e2 * v20.x);
            a1 += wyz0 * (wlo0 * q0.y + whi0 * q0.w + w_e2 * v20.y);
            a0 += wyz1 * (wlo1 * q1.x + whi1 * q1.z + w_e2 * v21.x);
            a1 += wyz1 * (wlo1 * q1.y + whi1 * q1.w + w_e2 * v21.y);
        }

        accpair[2 * (j & 1) + 0] = a0;
        accpair[2 * (j & 1) + 1] = a1;
        if (j & 1) {
            // float4 index = 2*quad + half: lane pair shares the 32B sector
            orow4[((j >> 1) << 1) + half] =
                make_float4(accpair[0], accpair[1], accpair[2], accpair[3]);
        }
    }
}

extern "C" void kernel_launch(void* const* d_in, const int* in_sizes, int n_in,
                              void* d_out, int out_size)
{
    const float* x = (const float*)d_in[0];
    const float* emb = (const float*)d_in[1];
    float* out = (float*)d_out;

    const int threads = 256;

    void* cnt_ptr = nullptr;
    cudaGetSymbolAddress(&cnt_ptr, g_cnt);
    cudaMemsetAsync(cnt_ptr, 0, (NBUCKETS + 1) * sizeof(unsigned int));

    scatter_kernel<<<(N_POINTS_C / 4) / threads, threads>>>(x);

    const int main_blocks = 2 * (MAIN_SLOTS + OVF_CAP) / threads;  // 16896
    hashgrid_kernel<<<main_blocks, threads>>>(emb, out);
}